// round 9
// baseline (speedup 1.0000x reference)
#include <cuda_runtime.h>
#include <cuda_bf16.h>
#include <cstdint>

#define Bn 16
#define Cn 64
#define Hn 160
#define Wn 160
#define HP 161
#define NLOG 9
#define NPIX (Bn * HP * HP)        // 414736 = 16 * 25921
#define NTILES (NPIX / 16)         // 25921 full 16-pixel warp tiles
#define NCONV 888                  // 148 * 6 persistent conv blocks
#define NTHR 128
#define NWARPS (NCONV * 4)
#define HW (Hn * Wn)
#define WROW 136                   // bf16 elems per nrow in W smem (272B, padded)
#define LU_STRIDE 65
#define SMEM_BYTES (64 * WROW * 2) // 17408 ; fp32 LU needs 16640 (fits)

__device__ double g_dlog[NLOG];
__device__ int    g_count = 0;

__device__ __forceinline__ void mma_bf16(float* d, const uint32_t* a, uint32_t b0, uint32_t b1) {
    asm volatile(
        "mma.sync.aligned.m16n8k16.row.col.f32.bf16.bf16.f32 "
        "{%0,%1,%2,%3}, {%4,%5,%6,%7}, {%8,%9}, {%0,%1,%2,%3};"
        : "+f"(d[0]), "+f"(d[1]), "+f"(d[2]), "+f"(d[3])
        : "r"(a[0]), "r"(a[1]), "r"(a[2]), "r"(a[3]), "r"(b0), "r"(b1));
}
__device__ __forceinline__ uint32_t pack_bf16x2(float hi, float lo) {
    uint32_t r;
    asm("cvt.rn.bf16x2.f32 %0, %1, %2;" : "=r"(r) : "f"(hi), "f"(lo));
    return r;
}

// ---- blocks 0..8: one fp32 LU each (log in fp64); last finisher writes logdet ----
__device__ void logdet_block(int r, const float* __restrict__ wgt,
                             const float* __restrict__ ldin,
                             float* __restrict__ outld,
                             unsigned char* smem_raw)
{
    float* A = reinterpret_cast<float*>(smem_raw);
    __shared__ float  s_val[2];
    __shared__ int    s_idx[2];
    __shared__ int    s_piv;
    __shared__ double s_acc;
    __shared__ int    s_ticket;

    const int tid = threadIdx.x;
    const int n   = (r == 0) ? 64 : (r <= 4 ? 32 : 16);
    const double pixw = (r == 0) ? (double)(Hn - 1) * (double)(Wn - 1)
                                 : (r <= 4 ? (double)(Wn - 1) : 1.0);
    auto chan = [&](int m) -> int {
        if (r == 0) return m;
        if (r <= 4) {
            const int t2[4][2] = {{2, 3}, {0, 1}, {1, 3}, {0, 2}};
            return 4 * (m >> 1) + t2[r - 1][m & 1];
        }
        const int t1[4] = {3, 2, 1, 0};
        return 4 * m + t1[r - 5];
    };

    for (int idx = tid; idx < n * n; idx += NTHR) {
        int ri = idx / n, ci = idx % n;
        A[ri * LU_STRIDE + ci] = wgt[chan(ri) * Cn + chan(ci)];
    }
    if (tid == 0) s_acc = 0.0;
    __syncthreads();

    for (int k = 0; k < n; k++) {
        float v = -1.0f;
        int vi = tid;
        if (tid >= k && tid < n) v = fabsf(A[tid * LU_STRIDE + k]);
        if (tid < 64) {
#pragma unroll
            for (int off = 16; off; off >>= 1) {
                float ov = __shfl_down_sync(0xffffffffu, v, off);
                int   oi = __shfl_down_sync(0xffffffffu, vi, off);
                if (ov > v) { v = ov; vi = oi; }
            }
            if ((tid & 31) == 0) { s_val[tid >> 5] = v; s_idx[tid >> 5] = vi; }
        }
        __syncthreads();
        if (tid == 0) {
            float bv = s_val[0]; int bi = s_idx[0];
            if (n > 32 && s_val[1] > bv) { bv = s_val[1]; bi = s_idx[1]; }
            s_piv = bi;
            s_acc += log((double)bv);
        }
        __syncthreads();
        const int piv = s_piv;
        if (piv != k && tid < n) {
            float t = A[k * LU_STRIDE + tid];
            A[k * LU_STRIDE + tid]   = A[piv * LU_STRIDE + tid];
            A[piv * LU_STRIDE + tid] = t;
        }
        __syncthreads();
        if (tid > k && tid < n) {
            float m = A[tid * LU_STRIDE + k] / A[k * LU_STRIDE + k];
            for (int c = k + 1; c < n; c++)
                A[tid * LU_STRIDE + c] -= m * A[k * LU_STRIDE + c];
        }
        __syncthreads();
    }

    if (tid == 0) {
        g_dlog[r] = s_acc * pixw;
        __threadfence();
        s_ticket = atomicAdd(&g_count, 1);
    }
    __syncthreads();
    if (s_ticket == NLOG - 1) {
        __threadfence();
        if (tid < Bn) {
            volatile double* gd = g_dlog;
            double s = 0.0;
#pragma unroll
            for (int k = 0; k < NLOG; k++) s += gd[k];
            outld[tid] = ldin[tid] + (float)s;
        }
        if (tid == 0) g_count = 0;
    }
}

// ---- main: warp-autonomous tiles; full-tile upfront gather (MLP=32); LDS.128 B frags ----
extern "C" __global__ void __launch_bounds__(NTHR)
ic1x1_kernel(const float* __restrict__ x, const float* __restrict__ wgt,
             const float* __restrict__ ldin,
             float* __restrict__ out, float* __restrict__ outld)
{
    extern __shared__ __align__(16) unsigned char smem_raw[];

    const int bx  = blockIdx.x;
    const int tid = threadIdx.x;
    if (bx < NLOG) { logdet_block(bx, wgt, ldin, outld, smem_raw); return; }

    __nv_bfloat16* wsm = reinterpret_cast<__nv_bfloat16*>(smem_raw);

    // ---- W fragment quartets: per (nrow, kt, q2): 16B = {hi k0,k0+1,k0+8,k0+9 | lo same} ----
    for (int g = tid; g < 64 * 16; g += NTHR) {
        const int nrow = g >> 4;
        const int kt   = (g >> 2) & 3;
        const int q2   = g & 3;
        const int k0   = kt * 16 + 2 * q2;
        const float* wr = wgt + nrow * 64;
        float w0 = wr[k0], w1 = wr[k0 + 1], w2 = wr[k0 + 8], w3 = wr[k0 + 9];
        float h0 = __bfloat162float(__float2bfloat16_rn(w0));
        float h1 = __bfloat162float(__float2bfloat16_rn(w1));
        float h2 = __bfloat162float(__float2bfloat16_rn(w2));
        float h3 = __bfloat162float(__float2bfloat16_rn(w3));
        uint4 v;
        v.x = pack_bf16x2(h1, h0);
        v.y = pack_bf16x2(h3, h2);
        v.z = pack_bf16x2(w1 - h1, w0 - h0);
        v.w = pack_bf16x2(w3 - h3, w2 - h2);
        *reinterpret_cast<uint4*>(&wsm[nrow * WROW + (kt * 4 + q2) * 8]) = v;
    }
    __syncthreads();

    const int lane = tid & 31;
    const int frow = lane >> 2;      // 0..7
    const int q2   = lane & 3;
    const int fkq  = q2 << 1;
    const int pp   = 1 - (q2 & 1);
    const int scb  = (q2 >> 1) * 4 + pp * 2;

    const uint32_t* wsm32 = reinterpret_cast<const uint32_t*>(wsm);
    const int wg = (bx - NLOG) * 4 + (tid >> 5);

    for (int t = wg; t < NTILES; t += NWARPS) {
        // ---- decode this thread's two pixels ----
        const int pidA = t * 16 + frow;
        const int pidB = pidA + 8;
        int bbA = pidA / (HP * HP); int rA = pidA - bbA * HP * HP;
        int iiA = rA / HP;          int jjA = rA - iiA * HP;
        int bbB = pidB / (HP * HP); int rB = pidB - bbB * HP * HP;
        int iiB = rB / HP;          int jjB = rB - iiB * HP;

        const int siA = iiA - pp, siB = iiB - pp;
        const bool rokA = (unsigned)siA < (unsigned)Hn;
        const bool rokB = (unsigned)siB < (unsigned)Hn;
        const bool ok0A = rokA && (unsigned)(jjA - 1) < (unsigned)Wn;
        const bool ok1A = rokA && jjA < Wn;
        const bool ok0B = rokB && (unsigned)(jjB - 1) < (unsigned)Wn;
        const bool ok1B = rokB && jjB < Wn;
        // single base per pixel; v0 path = base + (HW - 1) constant offset
        const float* bA = x + (size_t)bbA * (Cn * HW) + (scb * Hn + siA) * Wn + jjA;
        const float* bB = x + (size_t)bbB * (Cn * HW) + (scb * Hn + siB) * Wn + jjB;

        // ---- full-tile gather: all 32 loads in flight before any math ----
        float rv[32];   // [kt][e]: e = {pixA v0, pixA v1, pixB v0, pixB v1} x {h even, h odd}
#pragma unroll
        for (int hh = 0; hh < 8; hh++) {
            const int o  = hh * 8 * HW;
            rv[hh * 4 + 0] = ok0A ? bA[o + (HW - 1)] : 0.0f;
            rv[hh * 4 + 1] = ok1A ? bA[o]            : 0.0f;
            rv[hh * 4 + 2] = ok0B ? bB[o + (HW - 1)] : 0.0f;
            rv[hh * 4 + 3] = ok1B ? bB[o]            : 0.0f;
        }

        float d[8][4];
#pragma unroll
        for (int nt = 0; nt < 8; nt++)
#pragma unroll
            for (int r = 0; r < 4; r++) d[nt][r] = 0.0f;

#pragma unroll
        for (int kt = 0; kt < 4; kt++) {
            // convert this kt's 8 raw values -> A fragments
            uint32_t A_h[4], A_l[4];
#pragma unroll
            for (int e = 0; e < 4; e++) {
                // e = 0: pixA low-k (h even), 1: pixB low-k, 2: pixA high-k (h odd), 3: pixB high-k
                const int hh = kt * 2 + (e >> 1);
                const int px = e & 1;               // 0 = A, 1 = B
                const float v0 = rv[hh * 4 + px * 2 + 0];
                const float v1 = rv[hh * 4 + px * 2 + 1];
                const float h0 = __bfloat162float(__float2bfloat16_rn(v0));
                const float h1 = __bfloat162float(__float2bfloat16_rn(v1));
                A_h[e] = pack_bf16x2(h1, h0);
                A_l[e] = pack_bf16x2(v1 - h1, v0 - h0);
            }
#pragma unroll
            for (int nt = 0; nt < 8; nt++) {
                const int nrow = nt * 8 + frow;
                const uint32_t off = (uint32_t)(nrow * WROW + (kt * 4 + q2) * 8) >> 1;
                uint4 bb = *reinterpret_cast<const uint4*>(wsm32 + off);
                mma_bf16(d[nt], A_h, bb.x, bb.y);   // hh
                mma_bf16(d[nt], A_h, bb.z, bb.w);   // hi*lo
                mma_bf16(d[nt], A_l, bb.x, bb.y);   // lo*hi
            }
        }

        // ---- scatter through inverse shift (predication == region masks) ----
        float* obA = out + (size_t)bbA * (Cn * HW);
        float* obB = out + (size_t)bbB * (Cn * HW);
#pragma unroll
        for (int nt = 0; nt < 8; nt++) {
#pragma unroll
            for (int r = 0; r < 4; r++) {
                const int c = nt * 8 + fkq + (r & 1);
                const int P = (c >> 1) & 1, Q = c & 1;
                const int dc = (c & ~3) | ((1 - P) << 1) | (1 - Q);
                const int ii = (r & 2) ? iiB : iiA;
                const int jj = (r & 2) ? jjB : jjA;
                float* ob    = (r & 2) ? obB : obA;
                const int di = ii - (1 - P);
                const int dj = jj - (1 - Q);
                if ((unsigned)di < (unsigned)Hn && (unsigned)dj < (unsigned)Wn)
                    ob[(dc * Hn + di) * Wn + dj] = d[nt][r];
            }
        }
    }
}

extern "C" void kernel_launch(void* const* d_in, const int* in_sizes, int n_in,
                              void* d_out, int out_size)
{
    const float *x = nullptr, *ld = nullptr, *w = nullptr;
    for (int k = 0; k < n_in; k++) {
        if (in_sizes[k] == Cn * Cn)      w  = (const float*)d_in[k];
        else if (in_sizes[k] == Bn)      ld = (const float*)d_in[k];
        else                             x  = (const float*)d_in[k];
    }
    float* out   = (float*)d_out;
    float* outld = out + (out_size - Bn);

    ic1x1_kernel<<<NLOG + NCONV, NTHR, SMEM_BYTES>>>(x, w, ld, out, outld);
}

// round 10
// speedup vs baseline: 1.1087x; 1.1087x over previous
#include <cuda_runtime.h>
#include <cuda_bf16.h>
#include <cstdint>

#define Bn 16
#define Cn 64
#define Hn 160
#define Wn 160
#define HP 161
#define NLOG 9
#define NPIX (Bn * HP * HP)        // 414736
#define NT32 ((NPIX + 31) / 32)    // 12961 warp tiles of 32 pixels
#define NCONV 888                  // persistent conv blocks
#define NTHR 128
#define NWARPS (NCONV * 4)
#define HW (Hn * Wn)
#define WROW 136                   // bf16 elems per nrow in W smem (272B, padded)
#define LU_STRIDE 65
#define SMEM_BYTES (64 * WROW * 2) // 17408 ; fp32 LU needs 16640 (fits)

__device__ double g_dlog[NLOG];
__device__ int    g_count = 0;

__device__ __forceinline__ void mma_bf16(float* d, const uint32_t* a, uint32_t b0, uint32_t b1) {
    asm volatile(
        "mma.sync.aligned.m16n8k16.row.col.f32.bf16.bf16.f32 "
        "{%0,%1,%2,%3}, {%4,%5,%6,%7}, {%8,%9}, {%0,%1,%2,%3};"
        : "+f"(d[0]), "+f"(d[1]), "+f"(d[2]), "+f"(d[3])
        : "r"(a[0]), "r"(a[1]), "r"(a[2]), "r"(a[3]), "r"(b0), "r"(b1));
}
__device__ __forceinline__ uint32_t pack_bf16x2(float hi, float lo) {
    uint32_t r;
    asm("cvt.rn.bf16x2.f32 %0, %1, %2;" : "=r"(r) : "f"(hi), "f"(lo));
    return r;
}

// ---- blocks 0..8: one fp32 LU each (log in fp64); last finisher writes logdet ----
__device__ void logdet_block(int r, const float* __restrict__ wgt,
                             const float* __restrict__ ldin,
                             float* __restrict__ outld,
                             unsigned char* smem_raw)
{
    float* A = reinterpret_cast<float*>(smem_raw);
    __shared__ float  s_val[2];
    __shared__ int    s_idx[2];
    __shared__ int    s_piv;
    __shared__ double s_acc;
    __shared__ int    s_ticket;

    const int tid = threadIdx.x;
    const int n   = (r == 0) ? 64 : (r <= 4 ? 32 : 16);
    const double pixw = (r == 0) ? (double)(Hn - 1) * (double)(Wn - 1)
                                 : (r <= 4 ? (double)(Wn - 1) : 1.0);
    auto chan = [&](int m) -> int {
        if (r == 0) return m;
        if (r <= 4) {
            const int t2[4][2] = {{2, 3}, {0, 1}, {1, 3}, {0, 2}};
            return 4 * (m >> 1) + t2[r - 1][m & 1];
        }
        const int t1[4] = {3, 2, 1, 0};
        return 4 * m + t1[r - 5];
    };

    for (int idx = tid; idx < n * n; idx += NTHR) {
        int ri = idx / n, ci = idx % n;
        A[ri * LU_STRIDE + ci] = wgt[chan(ri) * Cn + chan(ci)];
    }
    if (tid == 0) s_acc = 0.0;
    __syncthreads();

    for (int k = 0; k < n; k++) {
        float v = -1.0f;
        int vi = tid;
        if (tid >= k && tid < n) v = fabsf(A[tid * LU_STRIDE + k]);
        if (tid < 64) {
#pragma unroll
            for (int off = 16; off; off >>= 1) {
                float ov = __shfl_down_sync(0xffffffffu, v, off);
                int   oi = __shfl_down_sync(0xffffffffu, vi, off);
                if (ov > v) { v = ov; vi = oi; }
            }
            if ((tid & 31) == 0) { s_val[tid >> 5] = v; s_idx[tid >> 5] = vi; }
        }
        __syncthreads();
        if (tid == 0) {
            float bv = s_val[0]; int bi = s_idx[0];
            if (n > 32 && s_val[1] > bv) { bv = s_val[1]; bi = s_idx[1]; }
            s_piv = bi;
            s_acc += log((double)bv);
        }
        __syncthreads();
        const int piv = s_piv;
        if (piv != k && tid < n) {
            float t = A[k * LU_STRIDE + tid];
            A[k * LU_STRIDE + tid]   = A[piv * LU_STRIDE + tid];
            A[piv * LU_STRIDE + tid] = t;
        }
        __syncthreads();
        if (tid > k && tid < n) {
            float m = A[tid * LU_STRIDE + k] / A[k * LU_STRIDE + k];
            for (int c = k + 1; c < n; c++)
                A[tid * LU_STRIDE + c] -= m * A[k * LU_STRIDE + c];
        }
        __syncthreads();
    }

    if (tid == 0) {
        g_dlog[r] = s_acc * pixw;
        __threadfence();
        s_ticket = atomicAdd(&g_count, 1);
    }
    __syncthreads();
    if (s_ticket == NLOG - 1) {
        __threadfence();
        if (tid < Bn) {
            volatile double* gd = g_dlog;
            double s = 0.0;
#pragma unroll
            for (int k = 0; k < NLOG; k++) s += gd[k];
            outld[tid] = ldin[tid] + (float)s;
        }
        if (tid == 0) g_count = 0;
    }
}

// ---- main: 32-pixel warp tiles (2 x m16), 16 independent MMA chains per warp ----
extern "C" __global__ void __launch_bounds__(NTHR)
ic1x1_kernel(const float* __restrict__ x, const float* __restrict__ wgt,
             const float* __restrict__ ldin,
             float* __restrict__ out, float* __restrict__ outld)
{
    extern __shared__ __align__(16) unsigned char smem_raw[];

    const int bx  = blockIdx.x;
    const int tid = threadIdx.x;
    if (bx < NLOG) { logdet_block(bx, wgt, ldin, outld, smem_raw); return; }

    __nv_bfloat16* wsm = reinterpret_cast<__nv_bfloat16*>(smem_raw);

    // ---- W fragment quartets: per (nrow, kt, q2): 16B = {hi k0,k0+1,k0+8,k0+9 | lo same} ----
    for (int g = tid; g < 64 * 16; g += NTHR) {
        const int nrow = g >> 4;
        const int kt   = (g >> 2) & 3;
        const int q2   = g & 3;
        const int k0   = kt * 16 + 2 * q2;
        const float* wr = wgt + nrow * 64;
        float w0 = wr[k0], w1 = wr[k0 + 1], w2 = wr[k0 + 8], w3 = wr[k0 + 9];
        float h0 = __bfloat162float(__float2bfloat16_rn(w0));
        float h1 = __bfloat162float(__float2bfloat16_rn(w1));
        float h2 = __bfloat162float(__float2bfloat16_rn(w2));
        float h3 = __bfloat162float(__float2bfloat16_rn(w3));
        uint4 v;
        v.x = pack_bf16x2(h1, h0);
        v.y = pack_bf16x2(h3, h2);
        v.z = pack_bf16x2(w1 - h1, w0 - h0);
        v.w = pack_bf16x2(w3 - h3, w2 - h2);
        *reinterpret_cast<uint4*>(&wsm[nrow * WROW + (kt * 4 + q2) * 8]) = v;
    }
    __syncthreads();

    const int lane = tid & 31;
    const int frow = lane >> 2;      // 0..7
    const int q2   = lane & 3;
    const int fkq  = q2 << 1;
    const int pp   = 1 - (q2 & 1);
    const int scb  = (q2 >> 1) * 4 + pp * 2;

    const uint32_t* wsm32 = reinterpret_cast<const uint32_t*>(wsm);
    const int wg = (bx - NLOG) * 4 + (tid >> 5);

    for (int t = wg; t < NT32; t += NWARPS) {
        // ---- decode 4 pixels: px = {A=+0, B=+8, C=+16, D=+24} + frow ----
        int  ii[4], jj[4];
        bool pv[4], ok0[4], ok1[4];
        const float* bas[4];
        float* ob[4];
#pragma unroll
        for (int px = 0; px < 4; px++) {
            int pid = t * 32 + px * 8 + frow;
            pv[px] = pid < NPIX;
            int pc  = pv[px] ? pid : 0;
            int bb  = pc / (HP * HP);
            int rr  = pc - bb * HP * HP;
            ii[px]  = rr / HP;
            jj[px]  = rr - ii[px] * HP;
            const int si = ii[px] - pp;
            const bool rok = pv[px] && (unsigned)si < (unsigned)Hn;
            ok0[px] = rok && (unsigned)(jj[px] - 1) < (unsigned)Wn;
            ok1[px] = rok && jj[px] < Wn;
            bas[px] = x   + (size_t)bb * (Cn * HW) + (scb * Hn + si) * Wn + jj[px];
            ob[px]  = out + (size_t)bb * (Cn * HW);
        }

        float d0[8][4], d1[8][4];
#pragma unroll
        for (int nt = 0; nt < 8; nt++)
#pragma unroll
            for (int r = 0; r < 4; r++) { d0[nt][r] = 0.0f; d1[nt][r] = 0.0f; }

#pragma unroll
        for (int kt = 0; kt < 4; kt++) {
            // gather + convert this kt's fragments for both m-tiles
            uint32_t A_h[4], A_l[4], C_h[4], C_l[4];
#pragma unroll
            for (int e = 0; e < 4; e++) {
                const int hh = kt * 2 + (e >> 1);
                const int o  = hh * 8 * HW;
                const int pxa = e & 1;          // tile0: px 0/1
                const int pxc = 2 + (e & 1);    // tile1: px 2/3
                {
                    const float v0 = ok0[pxa] ? bas[pxa][o + (HW - 1)] : 0.0f;
                    const float v1 = ok1[pxa] ? bas[pxa][o]            : 0.0f;
                    const float h0 = __bfloat162float(__float2bfloat16_rn(v0));
                    const float h1 = __bfloat162float(__float2bfloat16_rn(v1));
                    A_h[e] = pack_bf16x2(h1, h0);
                    A_l[e] = pack_bf16x2(v1 - h1, v0 - h0);
                }
                {
                    const float v0 = ok0[pxc] ? bas[pxc][o + (HW - 1)] : 0.0f;
                    const float v1 = ok1[pxc] ? bas[pxc][o]            : 0.0f;
                    const float h0 = __bfloat162float(__float2bfloat16_rn(v0));
                    const float h1 = __bfloat162float(__float2bfloat16_rn(v1));
                    C_h[e] = pack_bf16x2(h1, h0);
                    C_l[e] = pack_bf16x2(v1 - h1, v0 - h0);
                }
            }
#pragma unroll
            for (int nt = 0; nt < 8; nt++) {
                const int nrow = nt * 8 + frow;
                const uint32_t off = (uint32_t)(nrow * WROW + (kt * 4 + q2) * 8) >> 1;
                uint4 bb = *reinterpret_cast<const uint4*>(wsm32 + off);
                mma_bf16(d0[nt], A_h, bb.x, bb.y);
                mma_bf16(d1[nt], C_h, bb.x, bb.y);
                mma_bf16(d0[nt], A_h, bb.z, bb.w);
                mma_bf16(d1[nt], C_h, bb.z, bb.w);
                mma_bf16(d0[nt], A_l, bb.x, bb.y);
                mma_bf16(d1[nt], C_l, bb.x, bb.y);
            }
        }

        // ---- scatter both m-tiles through inverse shift ----
#pragma unroll
        for (int nt = 0; nt < 8; nt++) {
#pragma unroll
            for (int r = 0; r < 4; r++) {
                const int c = nt * 8 + fkq + (r & 1);
                const int P = (c >> 1) & 1, Q = c & 1;
                const int dc = (c & ~3) | ((1 - P) << 1) | (1 - Q);
#pragma unroll
                for (int tt = 0; tt < 2; tt++) {
                    const int px = tt * 2 + ((r >> 1) & 1);
                    const int di = ii[px] - (1 - P);
                    const int dj = jj[px] - (1 - Q);
                    if (pv[px] && (unsigned)di < (unsigned)Hn && (unsigned)dj < (unsigned)Wn)
                        ob[px][(dc * Hn + di) * Wn + dj] = tt ? d1[nt][r] : d0[nt][r];
                }
            }
        }
    }
}

extern "C" void kernel_launch(void* const* d_in, const int* in_sizes, int n_in,
                              void* d_out, int out_size)
{
    const float *x = nullptr, *ld = nullptr, *w = nullptr;
    for (int k = 0; k < n_in; k++) {
        if (in_sizes[k] == Cn * Cn)      w  = (const float*)d_in[k];
        else if (in_sizes[k] == Bn)      ld = (const float*)d_in[k];
        else                             x  = (const float*)d_in[k];
    }
    float* out   = (float*)d_out;
    float* outld = out + (out_size - Bn);

    ic1x1_kernel<<<NLOG + NCONV, NTHR, SMEM_BYTES>>>(x, w, ld, out, outld);
}

// round 11
// speedup vs baseline: 1.1366x; 1.0252x over previous
#include <cuda_runtime.h>
#include <cuda_bf16.h>
#include <cstdint>

#define Bn 16
#define Cn 64
#define Hn 160
#define Wn 160
#define HP 161
#define NLOG 9
#define NPIX (Bn * HP * HP)        // 414736
#define NT32 ((NPIX + 31) / 32)    // 12961 warp tiles of 32 pixels
#define NCONV 888
#define NTHR 128
#define NWARPS (NCONV * 4)
#define HW (Hn * Wn)
#define WROW 136                   // bf16 elems per nrow in W smem (272B, padded)
#define LU_STRIDE 65
#define SMEM_BYTES (64 * WROW * 2) // 17408 ; fp32 LU needs 16640 (fits)

__device__ double g_dlog[NLOG];
__device__ int    g_count = 0;

__device__ __forceinline__ void mma_bf16(float* d, const uint32_t* a, uint32_t b0, uint32_t b1) {
    asm volatile(
        "mma.sync.aligned.m16n8k16.row.col.f32.bf16.bf16.f32 "
        "{%0,%1,%2,%3}, {%4,%5,%6,%7}, {%8,%9}, {%0,%1,%2,%3};"
        : "+f"(d[0]), "+f"(d[1]), "+f"(d[2]), "+f"(d[3])
        : "r"(a[0]), "r"(a[1]), "r"(a[2]), "r"(a[3]), "r"(b0), "r"(b1));
}
__device__ __forceinline__ uint32_t pack_bf16x2(float hi, float lo) {
    uint32_t r;
    asm("cvt.rn.bf16x2.f32 %0, %1, %2;" : "=r"(r) : "f"(hi), "f"(lo));
    return r;
}

// ---- blocks 0..8: one fp32 LU each (log in fp64); last finisher writes logdet ----
__device__ void logdet_block(int r, const float* __restrict__ wgt,
                             const float* __restrict__ ldin,
                             float* __restrict__ outld,
                             unsigned char* smem_raw)
{
    float* A = reinterpret_cast<float*>(smem_raw);
    __shared__ float  s_val[2];
    __shared__ int    s_idx[2];
    __shared__ int    s_piv;
    __shared__ double s_acc;
    __shared__ int    s_ticket;

    const int tid = threadIdx.x;
    const int n   = (r == 0) ? 64 : (r <= 4 ? 32 : 16);
    const double pixw = (r == 0) ? (double)(Hn - 1) * (double)(Wn - 1)
                                 : (r <= 4 ? (double)(Wn - 1) : 1.0);
    auto chan = [&](int m) -> int {
        if (r == 0) return m;
        if (r <= 4) {
            const int t2[4][2] = {{2, 3}, {0, 1}, {1, 3}, {0, 2}};
            return 4 * (m >> 1) + t2[r - 1][m & 1];
        }
        const int t1[4] = {3, 2, 1, 0};
        return 4 * m + t1[r - 5];
    };

    for (int idx = tid; idx < n * n; idx += NTHR) {
        int ri = idx / n, ci = idx % n;
        A[ri * LU_STRIDE + ci] = wgt[chan(ri) * Cn + chan(ci)];
    }
    if (tid == 0) s_acc = 0.0;
    __syncthreads();

    for (int k = 0; k < n; k++) {
        float v = -1.0f;
        int vi = tid;
        if (tid >= k && tid < n) v = fabsf(A[tid * LU_STRIDE + k]);
        if (tid < 64) {
#pragma unroll
            for (int off = 16; off; off >>= 1) {
                float ov = __shfl_down_sync(0xffffffffu, v, off);
                int   oi = __shfl_down_sync(0xffffffffu, vi, off);
                if (ov > v) { v = ov; vi = oi; }
            }
            if ((tid & 31) == 0) { s_val[tid >> 5] = v; s_idx[tid >> 5] = vi; }
        }
        __syncthreads();
        if (tid == 0) {
            float bv = s_val[0]; int bi = s_idx[0];
            if (n > 32 && s_val[1] > bv) { bv = s_val[1]; bi = s_idx[1]; }
            s_piv = bi;
            s_acc += log((double)bv);
        }
        __syncthreads();
        const int piv = s_piv;
        if (piv != k && tid < n) {
            float t = A[k * LU_STRIDE + tid];
            A[k * LU_STRIDE + tid]   = A[piv * LU_STRIDE + tid];
            A[piv * LU_STRIDE + tid] = t;
        }
        __syncthreads();
        if (tid > k && tid < n) {
            float m = A[tid * LU_STRIDE + k] / A[k * LU_STRIDE + k];
            for (int c = k + 1; c < n; c++)
                A[tid * LU_STRIDE + c] -= m * A[k * LU_STRIDE + c];
        }
        __syncthreads();
    }

    if (tid == 0) {
        g_dlog[r] = s_acc * pixw;
        __threadfence();
        s_ticket = atomicAdd(&g_count, 1);
    }
    __syncthreads();
    if (s_ticket == NLOG - 1) {
        __threadfence();
        if (tid < Bn) {
            volatile double* gd = g_dlog;
            double s = 0.0;
#pragma unroll
            for (int k = 0; k < NLOG; k++) s += gd[k];
            outld[tid] = ldin[tid] + (float)s;
        }
        if (tid == 0) g_count = 0;
    }
}

// ---- main: 32-px warp tiles as 2 independent m16 GEMMs, cross-tile prefetch pipeline ----
extern "C" __global__ void __launch_bounds__(NTHR)
ic1x1_kernel(const float* __restrict__ x, const float* __restrict__ wgt,
             const float* __restrict__ ldin,
             float* __restrict__ out, float* __restrict__ outld)
{
    extern __shared__ __align__(16) unsigned char smem_raw[];

    const int bx  = blockIdx.x;
    const int tid = threadIdx.x;
    if (bx < NLOG) { logdet_block(bx, wgt, ldin, outld, smem_raw); return; }

    __nv_bfloat16* wsm = reinterpret_cast<__nv_bfloat16*>(smem_raw);

    // ---- W fragment quartets: per (nrow, kt, q2): 16B = {hi k0,k0+1,k0+8,k0+9 | lo same} ----
    for (int g = tid; g < 64 * 16; g += NTHR) {
        const int nrow = g >> 4;
        const int kt   = (g >> 2) & 3;
        const int q2g  = g & 3;
        const int k0   = kt * 16 + 2 * q2g;
        const float* wr = wgt + nrow * 64;
        float w0 = wr[k0], w1 = wr[k0 + 1], w2 = wr[k0 + 8], w3 = wr[k0 + 9];
        float h0 = __bfloat162float(__float2bfloat16_rn(w0));
        float h1 = __bfloat162float(__float2bfloat16_rn(w1));
        float h2 = __bfloat162float(__float2bfloat16_rn(w2));
        float h3 = __bfloat162float(__float2bfloat16_rn(w3));
        uint4 v;
        v.x = pack_bf16x2(h1, h0);
        v.y = pack_bf16x2(h3, h2);
        v.z = pack_bf16x2(w1 - h1, w0 - h0);
        v.w = pack_bf16x2(w3 - h3, w2 - h2);
        *reinterpret_cast<uint4*>(&wsm[nrow * WROW + (kt * 4 + q2g) * 8]) = v;
    }
    __syncthreads();

    const int lane = tid & 31;
    const int frow = lane >> 2;
    const int q2   = lane & 3;
    const int fkq  = q2 << 1;
    const int pp   = 1 - (q2 & 1);
    const int scb  = (q2 >> 1) * 4 + pp * 2;

    const uint32_t* wsm32 = reinterpret_cast<const uint32_t*>(wsm);
    const int wg = (bx - NLOG) * 4 + (tid >> 5);

    // decode 2 pixels (pxoff = 0 for A-pair, 16 for C-pair) and issue their 32 loads
    auto decode_load = [&](int t, int pxoff, int* pii, int* pjj, bool* ppv,
                           float** pob, float* buf) {
#pragma unroll
        for (int u = 0; u < 2; u++) {
            const int pid = t * 32 + pxoff + u * 8 + frow;
            const bool pvv = pid < NPIX;          // t >= NT32 => pid >= NPIX => false
            const int pc = pvv ? pid : 0;
            const int bb = pc / (HP * HP);
            const int rr = pc - bb * (HP * HP);
            const int iiv = rr / HP;
            const int jjv = rr - iiv * HP;
            pii[u] = iiv; pjj[u] = jjv; ppv[u] = pvv;
            pob[u] = out + (size_t)bb * (Cn * HW);
            const int si = iiv - pp;
            const bool rok = pvv && (unsigned)si < (unsigned)Hn;
            const bool o0 = rok && (unsigned)(jjv - 1) < (unsigned)Wn;
            const bool o1 = rok && jjv < Wn;
            const float* bas = x + (size_t)bb * (Cn * HW) + (scb * Hn + si) * Wn + jjv;
#pragma unroll
            for (int hh = 0; hh < 8; hh++) {
                const int o = hh * 8 * HW;
                buf[hh * 4 + u * 2 + 0] = o0 ? bas[o + (HW - 1)] : 0.0f;
                buf[hh * 4 + u * 2 + 1] = o1 ? bas[o]            : 0.0f;
            }
        }
    };

    // m16 x n64 x k64 split-bf16 GEMM from a 32-float raw buffer
    auto gemm = [&](const float* buf, float (*d)[4]) {
#pragma unroll
        for (int kt = 0; kt < 4; kt++) {
            uint32_t A_h[4], A_l[4];
#pragma unroll
            for (int e = 0; e < 4; e++) {
                const int hh = kt * 2 + (e >> 1);
                const int u  = e & 1;
                const float v0 = buf[hh * 4 + u * 2 + 0];
                const float v1 = buf[hh * 4 + u * 2 + 1];
                const float h0 = __bfloat162float(__float2bfloat16_rn(v0));
                const float h1 = __bfloat162float(__float2bfloat16_rn(v1));
                A_h[e] = pack_bf16x2(h1, h0);
                A_l[e] = pack_bf16x2(v1 - h1, v0 - h0);
            }
#pragma unroll
            for (int nt = 0; nt < 8; nt++) {
                const int nrow = nt * 8 + frow;
                const uint32_t off = (uint32_t)(nrow * WROW + (kt * 4 + q2) * 8) >> 1;
                uint4 bb = *reinterpret_cast<const uint4*>(wsm32 + off);
                mma_bf16(d[nt], A_h, bb.x, bb.y);
                mma_bf16(d[nt], A_h, bb.z, bb.w);
                mma_bf16(d[nt], A_l, bb.x, bb.y);
            }
        }
    };

    auto scatter = [&](float (*d)[4], const int* pii, const int* pjj,
                       const bool* ppv, float* const* pob) {
#pragma unroll
        for (int nt = 0; nt < 8; nt++) {
#pragma unroll
            for (int r = 0; r < 4; r++) {
                const int c = nt * 8 + fkq + (r & 1);
                const int P = (c >> 1) & 1, Q = c & 1;
                const int dc = (c & ~3) | ((1 - P) << 1) | (1 - Q);
                const int u  = (r >> 1) & 1;
                const int di = pii[u] - (1 - P);
                const int dj = pjj[u] - (1 - Q);
                if (ppv[u] && (unsigned)di < (unsigned)Hn && (unsigned)dj < (unsigned)Wn)
                    pob[u][(dc * Hn + di) * Wn + dj] = d[nt][r];
            }
        }
    };

    // ---- pipeline ----
    int  aii[2], ajj[2];  bool apv[2];  float* aob[2];  float rvA[32];
    decode_load(wg, 0, aii, ajj, apv, aob, rvA);

    for (int t = wg; t < NT32; t += NWARPS) {
        // C-pair loads: covered by gemm(rvA)
        int  cii[2], cjj[2];  bool cpv[2];  float* cob[2];  float rvC[32];
        decode_load(t, 16, cii, cjj, cpv, cob, rvC);

        float d0[8][4];
#pragma unroll
        for (int nt = 0; nt < 8; nt++)
#pragma unroll
            for (int r = 0; r < 4; r++) d0[nt][r] = 0.0f;
        gemm(rvA, d0);

        // next tile's A-pair loads: covered by scatter(d0) + gemm(rvC)
        int  nii[2], njj[2];  bool npv[2];  float* nob[2];  float nvA[32];
        decode_load(t + NWARPS, 0, nii, njj, npv, nob, nvA);

        scatter(d0, aii, ajj, apv, aob);

        float d1[8][4];
#pragma unroll
        for (int nt = 0; nt < 8; nt++)
#pragma unroll
            for (int r = 0; r < 4; r++) d1[nt][r] = 0.0f;
        gemm(rvC, d1);
        scatter(d1, cii, cjj, cpv, cob);

        // rotate prefetched state
#pragma unroll
        for (int u = 0; u < 2; u++) {
            aii[u] = nii[u]; ajj[u] = njj[u]; apv[u] = npv[u]; aob[u] = nob[u];
        }
#pragma unroll
        for (int e = 0; e < 32; e++) rvA[e] = nvA[e];
    }
}

extern "C" void kernel_launch(void* const* d_in, const int* in_sizes, int n_in,
                              void* d_out, int out_size)
{
    const float *x = nullptr, *ld = nullptr, *w = nullptr;
    for (int k = 0; k < n_in; k++) {
        if (in_sizes[k] == Cn * Cn)      w  = (const float*)d_in[k];
        else if (in_sizes[k] == Bn)      ld = (const float*)d_in[k];
        else                             x  = (const float*)d_in[k];
    }
    float* out   = (float*)d_out;
    float* outld = out + (out_size - Bn);

    ic1x1_kernel<<<NLOG + NCONV, NTHR, SMEM_BYTES>>>(x, w, ld, out, outld);
}

// round 12
// speedup vs baseline: 1.1508x; 1.0124x over previous
#include <cuda_runtime.h>
#include <cuda_fp16.h>
#include <cstdint>

#define Bn 16
#define Cn 64
#define Hn 160
#define Wn 160
#define HP 161
#define NLOG 9
#define NPIX (Bn * HP * HP)        // 414736
#define NT32 ((NPIX + 31) / 32)    // 12961 warp tiles of 32 pixels
#define NCONV 888
#define NTHR 128
#define NWARPS (NCONV * 4)
#define HW (Hn * Wn)
#define WROW2 72                   // fp16 elems per nrow in W smem (144B, padded)
#define LU_STRIDE 65
#define SMEM_BYTES 16640           // fp32 LU (64*65*4); W needs only 9216

__device__ double g_dlog[NLOG];
__device__ int    g_count = 0;

__device__ __forceinline__ void mma_f16(float* d, const uint32_t* a, uint32_t b0, uint32_t b1) {
    asm volatile(
        "mma.sync.aligned.m16n8k16.row.col.f32.f16.f16.f32 "
        "{%0,%1,%2,%3}, {%4,%5,%6,%7}, {%8,%9}, {%0,%1,%2,%3};"
        : "+f"(d[0]), "+f"(d[1]), "+f"(d[2]), "+f"(d[3])
        : "r"(a[0]), "r"(a[1]), "r"(a[2]), "r"(a[3]), "r"(b0), "r"(b1));
}
__device__ __forceinline__ uint32_t pack_f16x2(float hi, float lo) {
    uint32_t r;
    asm("cvt.rn.f16x2.f32 %0, %1, %2;" : "=r"(r) : "f"(hi), "f"(lo));
    return r;
}

// ---- blocks 0..8: one fp32 LU each (log in fp64); last finisher writes logdet ----
__device__ void logdet_block(int r, const float* __restrict__ wgt,
                             const float* __restrict__ ldin,
                             float* __restrict__ outld,
                             unsigned char* smem_raw)
{
    float* A = reinterpret_cast<float*>(smem_raw);
    __shared__ float  s_val[2];
    __shared__ int    s_idx[2];
    __shared__ int    s_piv;
    __shared__ double s_acc;
    __shared__ int    s_ticket;

    const int tid = threadIdx.x;
    const int n   = (r == 0) ? 64 : (r <= 4 ? 32 : 16);
    const double pixw = (r == 0) ? (double)(Hn - 1) * (double)(Wn - 1)
                                 : (r <= 4 ? (double)(Wn - 1) : 1.0);
    auto chan = [&](int m) -> int {
        if (r == 0) return m;
        if (r <= 4) {
            const int t2[4][2] = {{2, 3}, {0, 1}, {1, 3}, {0, 2}};
            return 4 * (m >> 1) + t2[r - 1][m & 1];
        }
        const int t1[4] = {3, 2, 1, 0};
        return 4 * m + t1[r - 5];
    };

    for (int idx = tid; idx < n * n; idx += NTHR) {
        int ri = idx / n, ci = idx % n;
        A[ri * LU_STRIDE + ci] = wgt[chan(ri) * Cn + chan(ci)];
    }
    if (tid == 0) s_acc = 0.0;
    __syncthreads();

    for (int k = 0; k < n; k++) {
        float v = -1.0f;
        int vi = tid;
        if (tid >= k && tid < n) v = fabsf(A[tid * LU_STRIDE + k]);
        if (tid < 64) {
#pragma unroll
            for (int off = 16; off; off >>= 1) {
                float ov = __shfl_down_sync(0xffffffffu, v, off);
                int   oi = __shfl_down_sync(0xffffffffu, vi, off);
                if (ov > v) { v = ov; vi = oi; }
            }
            if ((tid & 31) == 0) { s_val[tid >> 5] = v; s_idx[tid >> 5] = vi; }
        }
        __syncthreads();
        if (tid == 0) {
            float bv = s_val[0]; int bi = s_idx[0];
            if (n > 32 && s_val[1] > bv) { bv = s_val[1]; bi = s_idx[1]; }
            s_piv = bi;
            s_acc += log((double)bv);
        }
        __syncthreads();
        const int piv = s_piv;
        if (piv != k && tid < n) {
            float t = A[k * LU_STRIDE + tid];
            A[k * LU_STRIDE + tid]   = A[piv * LU_STRIDE + tid];
            A[piv * LU_STRIDE + tid] = t;
        }
        __syncthreads();
        if (tid > k && tid < n) {
            float m = A[tid * LU_STRIDE + k] / A[k * LU_STRIDE + k];
            for (int c = k + 1; c < n; c++)
                A[tid * LU_STRIDE + c] -= m * A[k * LU_STRIDE + c];
        }
        __syncthreads();
    }

    if (tid == 0) {
        g_dlog[r] = s_acc * pixw;
        __threadfence();
        s_ticket = atomicAdd(&g_count, 1);
    }
    __syncthreads();
    if (s_ticket == NLOG - 1) {
        __threadfence();
        if (tid < Bn) {
            volatile double* gd = g_dlog;
            double s = 0.0;
#pragma unroll
            for (int k = 0; k < NLOG; k++) s += gd[k];
            outld[tid] = ldin[tid] + (float)s;
        }
        if (tid == 0) g_count = 0;
    }
}

// ---- main: 32-px warp tiles, f16 exact-z-split 2-term GEMM, lean prefetch ----
extern "C" __global__ void __launch_bounds__(NTHR)
ic1x1_kernel(const float* __restrict__ x, const float* __restrict__ wgt,
             const float* __restrict__ ldin,
             float* __restrict__ out, float* __restrict__ outld)
{
    extern __shared__ __align__(16) unsigned char smem_raw[];

    const int bx  = blockIdx.x;
    const int tid = threadIdx.x;
    if (bx < NLOG) { logdet_block(bx, wgt, ldin, outld, smem_raw); return; }

    __half* wsm = reinterpret_cast<__half*>(smem_raw);

    // ---- W -> fp16 fragment pairs: per (nrow, kt, q2): 8B = {k0,k0+1 | k0+8,k0+9} ----
    for (int g = tid; g < 64 * 16; g += NTHR) {
        const int nrow = g >> 4;
        const int kt   = (g >> 2) & 3;
        const int q2g  = g & 3;
        const int k0   = kt * 16 + 2 * q2g;
        const float* wr = wgt + nrow * 64;
        uint2 v;
        v.x = pack_f16x2(wr[k0 + 1], wr[k0]);
        v.y = pack_f16x2(wr[k0 + 9], wr[k0 + 8]);
        *reinterpret_cast<uint2*>(&wsm[nrow * WROW2 + (kt * 4 + q2g) * 4]) = v;
    }
    __syncthreads();

    const int lane = tid & 31;
    const int frow = lane >> 2;
    const int q2   = lane & 3;
    const int fkq  = q2 << 1;
    const int pp   = 1 - (q2 & 1);
    const int scb  = (q2 >> 1) * 4 + pp * 2;

    const __half* wsmc = wsm;
    const int wg = (bx - NLOG) * 4 + (tid >> 5);

    // issue the 32 gathers of one half-tile (pxoff = 0 or 16) into buf
    auto load_half = [&](int t, int pxoff, float* buf) {
#pragma unroll
        for (int u = 0; u < 2; u++) {
            const int pid = t * 32 + pxoff + u * 8 + frow;
            const bool pvv = pid < NPIX;
            const int pc = pvv ? pid : 0;
            const int bb = pc / (HP * HP);
            const int rr = pc - bb * (HP * HP);
            const int iiv = rr / HP;
            const int jjv = rr - iiv * HP;
            const int si = iiv - pp;
            const bool rok = pvv && (unsigned)si < (unsigned)Hn;
            const bool o0 = rok && (unsigned)(jjv - 1) < (unsigned)Wn;
            const bool o1 = rok && jjv < Wn;
            const float* bas = x + (size_t)bb * (Cn * HW) + (scb * Hn + si) * Wn + jjv;
#pragma unroll
            for (int hh = 0; hh < 8; hh++) {
                const int o = hh * 8 * HW;
                buf[hh * 4 + u * 2 + 0] = o0 ? bas[o + (HW - 1)] : 0.0f;
                buf[hh * 4 + u * 2 + 1] = o1 ? bas[o]            : 0.0f;
            }
        }
    };

    // m16 x n64 x k64 GEMM, z split exactly into two fp16s, W in fp16
    auto gemm = [&](const float* buf, float (*d)[4]) {
#pragma unroll
        for (int kt = 0; kt < 4; kt++) {
            uint32_t A_h[4], A_l[4];
#pragma unroll
            for (int e = 0; e < 4; e++) {
                const int hh = kt * 2 + (e >> 1);
                const int u  = e & 1;
                const float v0 = buf[hh * 4 + u * 2 + 0];
                const float v1 = buf[hh * 4 + u * 2 + 1];
                const uint32_t ph = pack_f16x2(v1, v0);
                const float2 hf = __half22float2(*reinterpret_cast<const __half2*>(&ph));
                A_h[e] = ph;
                A_l[e] = pack_f16x2(v1 - hf.y, v0 - hf.x);
            }
#pragma unroll
            for (int nt = 0; nt < 8; nt++) {
                const int nrow = nt * 8 + frow;
                uint2 bb = *reinterpret_cast<const uint2*>(
                    wsmc + nrow * WROW2 + (kt * 4 + q2) * 4);
                mma_f16(d[nt], A_h, bb.x, bb.y);
                mma_f16(d[nt], A_l, bb.x, bb.y);
            }
        }
    };

    // scatter one half-tile; decode recomputed from t (cheap)
    auto scatter_half = [&](int t, int pxoff, float (*d)[4]) {
        int  ii2[2], jj2[2];
        bool pv2[2];
        float* ob2[2];
#pragma unroll
        for (int u = 0; u < 2; u++) {
            const int pid = t * 32 + pxoff + u * 8 + frow;
            pv2[u] = pid < NPIX;
            const int pc = pv2[u] ? pid : 0;
            const int bb = pc / (HP * HP);
            const int rr = pc - bb * (HP * HP);
            ii2[u] = rr / HP;
            jj2[u] = rr - ii2[u] * HP;
            ob2[u] = out + (size_t)bb * (Cn * HW);
        }
#pragma unroll
        for (int nt = 0; nt < 8; nt++) {
#pragma unroll
            for (int r = 0; r < 4; r++) {
                const int c = nt * 8 + fkq + (r & 1);
                const int P = (c >> 1) & 1, Q = c & 1;
                const int dc = (c & ~3) | ((1 - P) << 1) | (1 - Q);
                const int u  = (r >> 1) & 1;
                const int di = ii2[u] - (1 - P);
                const int dj = jj2[u] - (1 - Q);
                if (pv2[u] && (unsigned)di < (unsigned)Hn && (unsigned)dj < (unsigned)Wn)
                    ob2[u][(dc * Hn + di) * Wn + dj] = d[nt][r];
            }
        }
    };

    // ---- pipeline: prefetch only raw floats across tiles; single d buffer ----
    float rvA[32];
    load_half(wg, 0, rvA);

    for (int t = wg; t < NT32; t += NWARPS) {
        float rvC[32];
        load_half(t, 16, rvC);           // in flight over gemm(rvA)

        float d[8][4];
#pragma unroll
        for (int nt = 0; nt < 8; nt++)
#pragma unroll
            for (int r = 0; r < 4; r++) d[nt][r] = 0.0f;
        gemm(rvA, d);

        float nvA[32];
        load_half(t + NWARPS, 0, nvA);   // in flight over scatter + gemm(rvC)

        scatter_half(t, 0, d);

#pragma unroll
        for (int nt = 0; nt < 8; nt++)
#pragma unroll
            for (int r = 0; r < 4; r++) d[nt][r] = 0.0f;
        gemm(rvC, d);
        scatter_half(t, 16, d);

#pragma unroll
        for (int e = 0; e < 32; e++) rvA[e] = nvA[e];
    }
}

extern "C" void kernel_launch(void* const* d_in, const int* in_sizes, int n_in,
                              void* d_out, int out_size)
{
    const float *x = nullptr, *ld = nullptr, *w = nullptr;
    for (int k = 0; k < n_in; k++) {
        if (in_sizes[k] == Cn * Cn)      w  = (const float*)d_in[k];
        else if (in_sizes[k] == Bn)      ld = (const float*)d_in[k];
        else                             x  = (const float*)d_in[k];
    }
    float* out   = (float*)d_out;
    float* outld = out + (out_size - Bn);

    ic1x1_kernel<<<NLOG + NCONV, NTHR, SMEM_BYTES>>>(x, w, ld, out, outld);
}